// round 16
// baseline (speedup 1.0000x reference)
#include <cuda_runtime.h>
#include <cuda_fp16.h>
#include <cstdint>
#include <cstddef>

#define TT 2048
#define BB 64
#define SS 256
#define INK 64
#define DK 32
#define WK 96
#define CCH 64
#define LCH 32
#define TBS (TT*BB*SS)
#define PAD 36

// scan smem: 528B row stride (256 fp16 + 8 pad)
#define ROWB 528
#define SM_X0 0
#define SM_X1 (64 * ROWB)
#define SM_A0 (2 * 64 * ROWB)
#define SM_A1 (SM_A0 + 128 * ROWB)
#define SM_SCAN_TOT (SM_A1 + 128 * ROWB)   // 202752

__device__ float g_At[SS*SS];
__device__ float g_Wt[WK*SS];
__device__ float g_PA[SS*SS];
__device__ float g_PB[SS*SS];
__device__ float g_drive[TBS];
__device__ float g_localEnd[(CCH-1)*BB*SS];
__device__ float g_xstart[CCH*BB*SS];
__device__ unsigned g_sync;

// ---- f32x2 helpers ----
__device__ __forceinline__ void fma2(unsigned long long& a, unsigned long long x, unsigned long long w) {
    asm("fma.rn.f32x2 %0, %1, %2, %0;" : "+l"(a) : "l"(x), "l"(w));
}
__device__ __forceinline__ void add2(unsigned long long& a, unsigned long long x) {
    asm("add.rn.f32x2 %0, %1, %0;" : "+l"(a) : "l"(x));
}
__device__ __forceinline__ unsigned long long pack2(float lo, float hi) {
    unsigned long long r; asm("mov.b64 %0, {%1, %2};" : "=l"(r) : "f"(lo), "f"(hi)); return r;
}
__device__ __forceinline__ float2 unpack2(unsigned long long v) {
    float2 f; asm("mov.b64 {%0, %1}, %2;" : "=f"(f.x), "=f"(f.y) : "l"(v)); return f;
}

// ---- cluster / mma helpers ----
__device__ __forceinline__ uint32_t smem_u32(const void* p) {
    uint32_t a; asm("{ .reg .u64 t; cvta.to.shared.u64 t, %1; cvt.u32.u64 %0, t; }" : "=r"(a) : "l"(p)); return a;
}
__device__ __forceinline__ uint32_t ctarank() {
    uint32_t r; asm("mov.u32 %0, %%cluster_ctarank;" : "=r"(r)); return r;
}
__device__ __forceinline__ uint32_t mapa_peer(uint32_t addr, uint32_t peer) {
    uint32_t r; asm("mapa.shared::cluster.u32 %0, %1, %2;" : "=r"(r) : "r"(addr), "r"(peer)); return r;
}
__device__ __forceinline__ void st_cluster_b32(uint32_t addr, uint32_t v) {
    asm volatile("st.shared::cluster.b32 [%0], %1;" :: "r"(addr), "r"(v) : "memory");
}
#define CLUSTER_SYNC() do { \
    asm volatile("barrier.cluster.arrive.aligned;" ::: "memory"); \
    asm volatile("barrier.cluster.wait.aligned;"   ::: "memory"); \
} while (0)

__device__ __forceinline__ uint32_t lds_u32(uint32_t addr) {
    uint32_t v; asm volatile("ld.shared.b32 %0, [%1];" : "=r"(v) : "r"(addr)); return v;
}
__device__ __forceinline__ void mma16816(float c[4], const uint32_t a[4], const uint32_t b[2]) {
    asm volatile(
        "mma.sync.aligned.m16n8k16.row.col.f32.f16.f16.f32 "
        "{%0,%1,%2,%3}, {%4,%5,%6,%7}, {%8,%9}, {%0,%1,%2,%3};"
        : "+f"(c[0]), "+f"(c[1]), "+f"(c[2]), "+f"(c[3])
        : "r"(a[0]), "r"(a[1]), "r"(a[2]), "r"(a[3]), "r"(b[0]), "r"(b[1]));
}
__device__ __forceinline__ uint32_t h2pack(float lo, float hi) {
    __half2 h = __floats2half2_rn(lo, hi);
    return *(uint32_t*)&h;
}

// ---- prep ----
__global__ void __launch_bounds__(256) k_prep(const float* __restrict__ A,
                                              const float* __restrict__ Bw,
                                              const float* __restrict__ Ew) {
    int idx = blockIdx.x * blockDim.x + threadIdx.x;
    if (idx == 0) g_sync = 0u;
    if (idx < SS * SS) {
        int k = idx / SS, s = idx % SS;
        g_At[idx] = A[s * SS + k];
    } else {
        int j = idx - SS * SS;
        if (j < WK * SS) {
            int i = j / SS, s = j % SS;
            g_Wt[j] = (i < INK) ? Bw[s * INK + i] : Ew[s * DK + (i - INK)];
        }
    }
}

// ---- fp32 drive (proven) ----
template <int KTILES>
__device__ __forceinline__ void gemm_q(const float (*sx)[PAD], int roff, const float* wbase,
                                       unsigned long long a0[4], unsigned long long a1[4]) {
    float2 wv[8];
#pragma unroll
    for (int i = 0; i < 8; ++i) wv[i] = *(const float2*)(wbase + (size_t)i * SS);
#pragma unroll 1
    for (int kt = 0; kt < KTILES; ++kt) {
        float2 wn[8];
        if (kt < KTILES - 1) {
#pragma unroll
            for (int i = 0; i < 8; ++i) wn[i] = *(const float2*)(wbase + (size_t)((kt + 1) * 8 + i) * SS);
        }
#pragma unroll
        for (int i = 0; i < 8; ++i) {
            const int k = kt * 8 + i;
            unsigned long long w0 = pack2(wv[i].x, wv[i].x), w1 = pack2(wv[i].y, wv[i].y);
            const ulonglong2* xv = (const ulonglong2*)(&sx[k][roff]);
            ulonglong2 v0 = xv[0], v1 = xv[1];
            fma2(a0[0], v0.x, w0); fma2(a0[1], v0.y, w0); fma2(a0[2], v1.x, w0); fma2(a0[3], v1.y, w0);
            fma2(a1[0], v0.x, w1); fma2(a1[1], v0.y, w1); fma2(a1[2], v1.x, w1); fma2(a1[3], v1.y, w1);
        }
#pragma unroll
        for (int i = 0; i < 8; ++i) wv[i] = wn[i];
    }
}

__global__ void __launch_bounds__(512) k_drive(const float* __restrict__ U, const float* __restrict__ D) {
    __shared__ __align__(16) float sRow[WK][PAD];
    const int R0 = blockIdx.x * 32, tid = threadIdx.x;
    const int h = tid >> 7, lane = tid & 127, s0 = 2 * lane, roff = 8 * h;
    for (int e = tid; e < 32 * WK; e += 512) {
        int r = e / WK, i = e % WK;
        size_t R = (size_t)(R0 + r);
        sRow[i][r] = (i < INK) ? U[R * INK + i] : D[R * DK + (i - INK)];
    }
    __syncthreads();
    unsigned long long a0[4], a1[4];
#pragma unroll
    for (int q = 0; q < 4; ++q) { a0[q] = 0ull; a1[q] = 0ull; }
    gemm_q<WK / 8>(sRow, roff, g_Wt + s0, a0, a1);
#pragma unroll
    for (int q = 0; q < 4; ++q) {
        float2 f0 = unpack2(a0[q]), f1 = unpack2(a1[q]);
        *(float2*)(&g_drive[(size_t)(R0 + roff + 2 * q) * SS + s0])     = make_float2(f0.x, f1.x);
        *(float2*)(&g_drive[(size_t)(R0 + roff + 2 * q + 1) * SS + s0]) = make_float2(f0.y, f1.y);
    }
}

// ---- powers: (A^T)^32 ----
__global__ void __launch_bounds__(256) k_powers() {
    __shared__ float sRow[2][SS];
    const int tid = threadIdx.x, k0 = blockIdx.x * 2;
    const float* src = g_At;
    float* dst = g_PA;
#pragma unroll 1
    for (int step = 0; step < 5; ++step) {
        sRow[0][tid] = src[(size_t)k0 * SS + tid];
        sRow[1][tid] = src[(size_t)(k0 + 1) * SS + tid];
        __syncthreads();
        float a0 = 0.f, a1 = 0.f;
#pragma unroll 4
        for (int j = 0; j < SS; ++j) {
            float b = src[(size_t)j * SS + tid];
            a0 = fmaf(sRow[0][j], b, a0);
            a1 = fmaf(sRow[1][j], b, a1);
        }
        dst[(size_t)k0 * SS + tid] = a0;
        dst[(size_t)(k0 + 1) * SS + tid] = a1;
        __syncthreads();
        if (tid == 0) {
            __threadfence();
            atomicAdd(&g_sync, 1u);
            unsigned tgt = 128u * (unsigned)(step + 1);
            while (*((volatile unsigned*)&g_sync) < tgt) { __nanosleep(64); }
        }
        __syncthreads();
        src = dst;
        dst = (dst == g_PA) ? g_PB : g_PA;
    }
}

// ---- warp-MMA scan: 512 threads, 16 warps; warp = 2 n-tiles x 2 m-tiles ----
// 2-CTA cluster per chunk; CTA rank owns output cols [rank*128, +128).
template <int MODE>
__global__ void __launch_bounds__(512) __cluster_dims__(2, 1, 1)
k_scan_mma(const float* __restrict__ Aw, float* __restrict__ out, int dup) {
    extern __shared__ __align__(16) char sm[];
    __shared__ float smax[17];
    const uint32_t sb = smem_u32(sm);
    const int tid = threadIdx.x;
    const int w = tid >> 5, lane = tid & 31;
    const uint32_t rank = ctarank();
    const int chunk = blockIdx.x >> 1;

    // A rows [rank*128, +128) x K=256, fp16 split-2
    for (int e = tid; e < 128 * 256; e += 512) {
        int r = e >> 8, k = e & 255;
        float v = Aw[(size_t)((int)rank * 128 + r) * SS + k];
        __half q0 = __float2half_rn(v);
        __half q1 = __float2half_rn(v - __half2float(q0));
        *(__half*)(sm + SM_A0 + r * ROWB + k * 2) = q0;
        *(__half*)(sm + SM_A1 + r * ROWB + k * 2) = q1;
    }

    // per-chunk max|x_start| (both CTAs compute identically)
    const float* xsrc = (MODE == 1) ? (g_drive + (size_t)(chunk * LCH) * BB * SS)
                                    : (g_xstart + (size_t)chunk * BB * SS);
    {
        float mymax = 0.f;
        for (int e = tid; e < 64 * 256; e += 512) mymax = fmaxf(mymax, fabsf(xsrc[e]));
#pragma unroll
        for (int o = 16; o; o >>= 1) mymax = fmaxf(mymax, __shfl_xor_sync(0xFFFFFFFFu, mymax, o));
        if (lane == 0) smax[w] = mymax;
        __syncthreads();
        if (tid == 0) {
            float m = smax[0];
#pragma unroll
            for (int i = 1; i < 16; ++i) m = fmaxf(m, smax[i]);
            smax[16] = m;
        }
        __syncthreads();
    }
    const float maxv = smax[16];
    const int ex = (maxv > 1e-30f) ? ilogbf(maxv) : 0;
    const float sc  = ldexpf(1.0f, -ex);   // exact power of 2
    const float inv = ldexpf(1.0f,  ex);

    // X init (scaled) fp16 split-2
    for (int e = tid; e < 64 * 256; e += 512) {
        int b = e >> 8, k = e & 255;
        float v = xsrc[(size_t)b * SS + k] * sc;
        __half q0 = __float2half_rn(v);
        __half q1 = __float2half_rn(v - __half2float(q0));
        *(__half*)(sm + SM_X0 + b * ROWB + k * 2) = q0;
        *(__half*)(sm + SM_X1 + b * ROWB + k * 2) = q1;
    }
    __syncthreads();
    CLUSTER_SYNC();   // both CTAs' X + A tiles ready

    const uint32_t peerX = mapa_peer(sb, rank ^ 1u);

    // fragment index pieces (PTX m16n8k16 tables, direct addressing)
    const int qrow = lane >> 2;
    const uint32_t cb = (uint32_t)(lane & 3) * 4;
    const int n0 = (w & 7) * 16;            // 2 n-tiles (16 cols) per warp
    const int mh = w >> 3;                  // m-half: rows [mh*32, +32) = 2 m-tiles
    const int colg = (int)rank * 128 + n0 + 2 * (lane & 3);

    const int j0 = (MODE == 1) ? 1 : 0;

#pragma unroll 1
    for (int j = j0; j < LCH; ++j) {
        const int t = chunk * LCH + j;

        float acc[2][2][4];
#pragma unroll
        for (int nt = 0; nt < 2; ++nt)
#pragma unroll
            for (int m = 0; m < 2; ++m)
#pragma unroll
                for (int q = 0; q < 4; ++q) acc[nt][m][q] = 0.f;

        // prefetch drive (raw fp32; scaled at add time)
        float2 dv[2][2][2];
        const float* drp = g_drive + (size_t)t * BB * SS;
#pragma unroll
        for (int nt = 0; nt < 2; ++nt)
#pragma unroll
            for (int m = 0; m < 2; ++m)
#pragma unroll
                for (int i = 0; i < 2; ++i)
                    dv[nt][m][i] = *(const float2*)(drp + (size_t)(mh * 32 + m * 16 + qrow + i * 8) * SS + colg + nt * 8);

#pragma unroll 2
        for (int kt = 0; kt < 16; ++kt) {
            const uint32_t kb = (uint32_t)kt * 32;
            uint32_t ax0[2][4], ax1[2][4];
#pragma unroll
            for (int m = 0; m < 2; ++m) {
                uint32_t b0a = sb + SM_X0 + (uint32_t)(mh * 32 + m * 16 + qrow) * ROWB + cb + kb;
                uint32_t b1a = sb + SM_X1 + (uint32_t)(mh * 32 + m * 16 + qrow) * ROWB + cb + kb;
                ax0[m][0] = lds_u32(b0a);
                ax0[m][1] = lds_u32(b0a + 8u * ROWB);
                ax0[m][2] = lds_u32(b0a + 16u);
                ax0[m][3] = lds_u32(b0a + 8u * ROWB + 16u);
                ax1[m][0] = lds_u32(b1a);
                ax1[m][1] = lds_u32(b1a + 8u * ROWB);
                ax1[m][2] = lds_u32(b1a + 16u);
                ax1[m][3] = lds_u32(b1a + 8u * ROWB + 16u);
            }
            uint32_t bb0[2][2], bb1[2][2];
#pragma unroll
            for (int nt = 0; nt < 2; ++nt) {
                uint32_t ba0 = sb + SM_A0 + (uint32_t)(n0 + nt * 8 + qrow) * ROWB + cb + kb;
                uint32_t ba1 = sb + SM_A1 + (uint32_t)(n0 + nt * 8 + qrow) * ROWB + cb + kb;
                bb0[nt][0] = lds_u32(ba0);
                bb0[nt][1] = lds_u32(ba0 + 16u);
                bb1[nt][0] = lds_u32(ba1);
                bb1[nt][1] = lds_u32(ba1 + 16u);
            }
#pragma unroll
            for (int nt = 0; nt < 2; ++nt)
#pragma unroll
                for (int m = 0; m < 2; ++m) {
                    mma16816(acc[nt][m], ax0[m], bb0[nt]);   // X0*A0
                    mma16816(acc[nt][m], ax1[m], bb0[nt]);   // X1*A0
                    mma16816(acc[nt][m], ax0[m], bb1[nt]);   // X0*A1
                }
        }

        CLUSTER_SYNC();   // BOTH CTAs finished reading X before anyone overwrites it

        // finalize own tiles: write local + peer smem (DSMEM), outputs to gmem
#pragma unroll
        for (int nt = 0; nt < 2; ++nt)
#pragma unroll
            for (int m = 0; m < 2; ++m)
#pragma unroll
                for (int i = 0; i < 2; ++i) {
                    float v0 = acc[nt][m][2 * i]     + dv[nt][m][i].x * sc;
                    float v1 = acc[nt][m][2 * i + 1] + dv[nt][m][i].y * sc;
                    const int row  = mh * 32 + m * 16 + qrow + i * 8;
                    const int kcol = colg + nt * 8;

                    if (MODE == 3) {
                        float* o1 = out + (size_t)t * BB * SS + (size_t)row * SS + kcol;
                        *(float2*)o1 = make_float2(v0 * inv, v1 * inv);
                        if (dup) *(float2*)(o1 + (size_t)TBS) = make_float2(v0 * inv, v1 * inv);
                    }
                    if (MODE == 1 && j == LCH - 1) {
                        float* le = g_localEnd + (size_t)chunk * BB * SS + (size_t)row * SS + kcol;
                        *(float2*)le = make_float2(v0 * inv, v1 * inv);
                    }

                    __half h0 = __float2half_rn(v0);
                    __half h1 = __float2half_rn(v1);
                    uint32_t p0 = h2pack(v0, v1);
                    uint32_t p1 = h2pack(v0 - __half2float(h0), v1 - __half2float(h1));
                    const uint32_t off = (uint32_t)row * ROWB + (uint32_t)kcol * 2;
                    *(uint32_t*)(sm + SM_X0 + off) = p0;
                    *(uint32_t*)(sm + SM_X1 + off) = p1;
                    st_cluster_b32(peerX + SM_X0 + off, p0);
                    st_cluster_b32(peerX + SM_X1 + off, p1);
                }

        CLUSTER_SYNC();   // all local+peer X writes visible before next step's reads
    }
}

// ---- pass2: boundary recurrence (fp32, proven) ----
__global__ void __launch_bounds__(128) k_pass2(const float* __restrict__ x0) {
    const int b0 = blockIdx.x * 2;
    const int s0 = 2 * threadIdx.x;
    __shared__ __align__(8) float sxp[SS][2];

    float2 vA = *(const float2*)(&x0[(size_t)b0 * SS + s0]);
    float2 vB = *(const float2*)(&x0[(size_t)(b0 + 1) * SS + s0]);
    sxp[s0][0] = vA.x;     sxp[s0][1] = vB.x;
    sxp[s0 + 1][0] = vA.y; sxp[s0 + 1][1] = vB.y;
    *(float2*)(&g_xstart[((size_t)b0) * SS + s0])       = vA;
    *(float2*)(&g_xstart[((size_t)(b0 + 1)) * SS + s0]) = vB;
    __syncthreads();

#pragma unroll 1
    for (int c = 1; c < CCH; ++c) {
        float2 eA = *(const float2*)(&g_localEnd[((size_t)(c - 1) * BB + b0) * SS + s0]);
        float2 eB = *(const float2*)(&g_localEnd[((size_t)(c - 1) * BB + b0 + 1) * SS + s0]);
        unsigned long long a0[4], a1[4];
#pragma unroll
        for (int u = 0; u < 4; ++u) { a0[u] = 0ull; a1[u] = 0ull; }
        const float* wp = g_PA + s0;
#pragma unroll 2
        for (int k = 0; k < SS; k += 4) {
#pragma unroll
            for (int u = 0; u < 4; ++u) {
                float2 wv = *(const float2*)(wp + (size_t)(k + u) * SS);
                unsigned long long xp = *(const unsigned long long*)(&sxp[k + u][0]);
                fma2(a0[u], xp, pack2(wv.x, wv.x));
                fma2(a1[u], xp, pack2(wv.y, wv.y));
            }
        }
        add2(a0[0], a0[1]); add2(a0[2], a0[3]); add2(a0[0], a0[2]);
        add2(a1[0], a1[1]); add2(a1[2], a1[3]); add2(a1[0], a1[2]);
        float2 f0 = unpack2(a0[0]), f1 = unpack2(a1[0]);
        f0.x += eA.x; f0.y += eB.x;
        f1.x += eA.y; f1.y += eB.y;
        __syncthreads();
        sxp[s0][0] = f0.x;     sxp[s0][1] = f0.y;
        sxp[s0 + 1][0] = f1.x; sxp[s0 + 1][1] = f1.y;
        __syncthreads();
        *(float2*)(&g_xstart[((size_t)c * BB + b0) * SS + s0])     = make_float2(f0.x, f1.x);
        *(float2*)(&g_xstart[((size_t)c * BB + b0 + 1) * SS + s0]) = make_float2(f0.y, f1.y);
    }
}

// ---- launcher ----
extern "C" void kernel_launch(void* const* d_in, const int* in_sizes, int n_in,
                              void* d_out, int out_size) {
    const float* x  = (const float*)d_in[0];
    const float* U  = (const float*)d_in[1];
    const float* D  = (const float*)d_in[2];
    const float* Aw = (const float*)d_in[3];
    const float* Bw = (const float*)d_in[4];
    const float* Ew = (const float*)d_in[5];
    float* out = (float*)d_out;
    int dup = (out_size >= 2 * TBS) ? 1 : 0;

    cudaFuncSetAttribute(k_scan_mma<1>, cudaFuncAttributeMaxDynamicSharedMemorySize, SM_SCAN_TOT);
    cudaFuncSetAttribute(k_scan_mma<3>, cudaFuncAttributeMaxDynamicSharedMemorySize, SM_SCAN_TOT);

    k_prep<<<(SS * SS + WK * SS + 255) / 256, 256>>>(Aw, Bw, Ew);     // 0
    k_drive<<<(TT * BB) / 32, 512>>>(U, D);                            // 1
    k_powers<<<SS / 2, 256>>>();                                       // 2
    k_scan_mma<1><<<(CCH - 1) * 2, 512, SM_SCAN_TOT>>>(Aw, out, 0);    // 3 (pass1)
    k_pass2<<<BB / 2, 128>>>(x);                                       // 4
    k_scan_mma<3><<<CCH * 2, 512, SM_SCAN_TOT>>>(Aw, out, dup);        // 5 (pass3)
}

// round 17
// speedup vs baseline: 1.0844x; 1.0844x over previous
#include <cuda_runtime.h>
#include <cuda_fp16.h>
#include <cstdint>
#include <cstddef>

#define TT 2048
#define BB 64
#define SS 256
#define INK 64
#define DK 32
#define WK 96
#define CCH 64
#define LCH 32
#define TBS (TT*BB*SS)

// scan smem: 528B row stride (256 fp16 + 8 pad)
#define ROWB 528
#define SM_X0 0
#define SM_X1 (64 * ROWB)
#define SM_A0 (2 * 64 * ROWB)
#define SM_A1 (SM_A0 + 128 * ROWB)
#define SM_SCAN_TOT (SM_A1 + 128 * ROWB)   // 202752

// drive smem: 208B row stride (96 fp16 + 8 pad)
#define ROWD 208
#define DM_W0 0
#define DM_W1 (128 * ROWD)
#define DM_I0 (2 * 128 * ROWD)
#define DM_I1 (3 * 128 * ROWD)
#define DM_TOT (4 * 128 * ROWD)            // 106496

__device__ float g_At[SS*SS];
__device__ float g_PA[SS*SS];
__device__ float g_PB[SS*SS];
__device__ float g_drive[TBS];
__device__ float g_localEnd[(CCH-1)*BB*SS];
__device__ float g_xstart[CCH*BB*SS];
__device__ unsigned g_sync;

// ---- f32x2 helpers (pass2) ----
__device__ __forceinline__ void fma2(unsigned long long& a, unsigned long long x, unsigned long long w) {
    asm("fma.rn.f32x2 %0, %1, %2, %0;" : "+l"(a) : "l"(x), "l"(w));
}
__device__ __forceinline__ void add2(unsigned long long& a, unsigned long long x) {
    asm("add.rn.f32x2 %0, %1, %0;" : "+l"(a) : "l"(x));
}
__device__ __forceinline__ unsigned long long pack2(float lo, float hi) {
    unsigned long long r; asm("mov.b64 %0, {%1, %2};" : "=l"(r) : "f"(lo), "f"(hi)); return r;
}
__device__ __forceinline__ float2 unpack2(unsigned long long v) {
    float2 f; asm("mov.b64 {%0, %1}, %2;" : "=f"(f.x), "=f"(f.y) : "l"(v)); return f;
}

// ---- cluster / mma helpers ----
__device__ __forceinline__ uint32_t smem_u32(const void* p) {
    uint32_t a; asm("{ .reg .u64 t; cvta.to.shared.u64 t, %1; cvt.u32.u64 %0, t; }" : "=r"(a) : "l"(p)); return a;
}
__device__ __forceinline__ uint32_t ctarank() {
    uint32_t r; asm("mov.u32 %0, %%cluster_ctarank;" : "=r"(r)); return r;
}
__device__ __forceinline__ uint32_t mapa_peer(uint32_t addr, uint32_t peer) {
    uint32_t r; asm("mapa.shared::cluster.u32 %0, %1, %2;" : "=r"(r) : "r"(addr), "r"(peer)); return r;
}
__device__ __forceinline__ void st_cluster_b32(uint32_t addr, uint32_t v) {
    asm volatile("st.shared::cluster.b32 [%0], %1;" :: "r"(addr), "r"(v) : "memory");
}
#define CLUSTER_SYNC() do { \
    asm volatile("barrier.cluster.arrive.aligned;" ::: "memory"); \
    asm volatile("barrier.cluster.wait.aligned;"   ::: "memory"); \
} while (0)

__device__ __forceinline__ uint32_t lds_u32(uint32_t addr) {
    uint32_t v; asm volatile("ld.shared.b32 %0, [%1];" : "=r"(v) : "r"(addr)); return v;
}
__device__ __forceinline__ void mma16816(float c[4], const uint32_t a[4], const uint32_t b[2]) {
    asm volatile(
        "mma.sync.aligned.m16n8k16.row.col.f32.f16.f16.f32 "
        "{%0,%1,%2,%3}, {%4,%5,%6,%7}, {%8,%9}, {%0,%1,%2,%3};"
        : "+f"(c[0]), "+f"(c[1]), "+f"(c[2]), "+f"(c[3])
        : "r"(a[0]), "r"(a[1]), "r"(a[2]), "r"(a[3]), "r"(b[0]), "r"(b[1]));
}
__device__ __forceinline__ uint32_t h2pack(float lo, float hi) {
    __half2 h = __floats2half2_rn(lo, hi);
    return *(uint32_t*)&h;
}

// ---- prep ----
__global__ void __launch_bounds__(256) k_prep(const float* __restrict__ A) {
    int idx = blockIdx.x * blockDim.x + threadIdx.x;
    if (idx == 0) g_sync = 0u;
    if (idx < SS * SS) {
        int k = idx / SS, s = idx % SS;
        g_At[idx] = A[s * SS + k];
    }
}

// ---- drive via warp-MMA: drive[r,s] = In[r,:]·W[s,:]^T, fp16 split-2, 3 terms ----
// CTA = 128 rows x 128 cols. 512 threads, 16 warps = 8 n-groups x 2 m-halves.
__global__ void __launch_bounds__(512) k_drive_mma(const float* __restrict__ U,
                                                   const float* __restrict__ D,
                                                   const float* __restrict__ Bw,
                                                   const float* __restrict__ Ew) {
    extern __shared__ __align__(16) char sm[];
    const uint32_t sb = smem_u32(sm);
    const int tid = threadIdx.x;
    const int w = tid >> 5, lane = tid & 31;
    const int rb = blockIdx.x >> 1;        // row block (128 rows)
    const int C0 = (blockIdx.x & 1) * 128; // col half
    const int R0 = rb * 128;

    // W[s][i] tiles (s = C0..C0+127), fp16 split-2
    for (int e = tid; e < 128 * WK; e += 512) {
        int n = e / WK, i = e % WK;
        float v = (i < INK) ? Bw[(size_t)(C0 + n) * INK + i] : Ew[(size_t)(C0 + n) * DK + (i - INK)];
        __half q0 = __float2half_rn(v);
        __half q1 = __float2half_rn(v - __half2float(q0));
        *(__half*)(sm + DM_W0 + n * ROWD + i * 2) = q0;
        *(__half*)(sm + DM_W1 + n * ROWD + i * 2) = q1;
    }
    // input rows [R0, +128), fp16 split-2
    for (int e = tid; e < 128 * WK; e += 512) {
        int r = e / WK, i = e % WK;
        size_t R = (size_t)(R0 + r);
        float v = (i < INK) ? U[R * INK + i] : D[R * DK + (i - INK)];
        __half q0 = __float2half_rn(v);
        __half q1 = __float2half_rn(v - __half2float(q0));
        *(__half*)(sm + DM_I0 + r * ROWD + i * 2) = q0;
        *(__half*)(sm + DM_I1 + r * ROWD + i * 2) = q1;
    }
    __syncthreads();

    const int qrow = lane >> 2;
    const uint32_t cb = (uint32_t)(lane & 3) * 4;
    const int n0 = (w & 7) * 16;           // warp's 2 n-tiles
    const int mh = w >> 3;                 // m-half: rows [mh*64, +64) = 4 m-tiles

    float acc[2][4][4];
#pragma unroll
    for (int nt = 0; nt < 2; ++nt)
#pragma unroll
        for (int m = 0; m < 4; ++m)
#pragma unroll
            for (int q = 0; q < 4; ++q) acc[nt][m][q] = 0.f;

#pragma unroll
    for (int kt = 0; kt < WK / 16; ++kt) {    // 6 kt
        const uint32_t kb = (uint32_t)kt * 32;
        uint32_t ax0[4][4], ax1[4][4];
#pragma unroll
        for (int m = 0; m < 4; ++m) {
            uint32_t a0 = sb + DM_I0 + (uint32_t)(mh * 64 + m * 16 + qrow) * ROWD + cb + kb;
            uint32_t a1 = sb + DM_I1 + (uint32_t)(mh * 64 + m * 16 + qrow) * ROWD + cb + kb;
            ax0[m][0] = lds_u32(a0);
            ax0[m][1] = lds_u32(a0 + 8u * ROWD);
            ax0[m][2] = lds_u32(a0 + 16u);
            ax0[m][3] = lds_u32(a0 + 8u * ROWD + 16u);
            ax1[m][0] = lds_u32(a1);
            ax1[m][1] = lds_u32(a1 + 8u * ROWD);
            ax1[m][2] = lds_u32(a1 + 16u);
            ax1[m][3] = lds_u32(a1 + 8u * ROWD + 16u);
        }
        uint32_t bb0[2][2], bb1[2][2];
#pragma unroll
        for (int nt = 0; nt < 2; ++nt) {
            uint32_t b0 = sb + DM_W0 + (uint32_t)(n0 + nt * 8 + qrow) * ROWD + cb + kb;
            uint32_t b1 = sb + DM_W1 + (uint32_t)(n0 + nt * 8 + qrow) * ROWD + cb + kb;
            bb0[nt][0] = lds_u32(b0);
            bb0[nt][1] = lds_u32(b0 + 16u);
            bb1[nt][0] = lds_u32(b1);
            bb1[nt][1] = lds_u32(b1 + 16u);
        }
#pragma unroll
        for (int nt = 0; nt < 2; ++nt)
#pragma unroll
            for (int m = 0; m < 4; ++m) {
                mma16816(acc[nt][m], ax0[m], bb0[nt]);   // I0*W0
                mma16816(acc[nt][m], ax1[m], bb0[nt]);   // I1*W0
                mma16816(acc[nt][m], ax0[m], bb1[nt]);   // I0*W1
            }
    }

    const int colg = C0 + n0 + 2 * (lane & 3);
#pragma unroll
    for (int nt = 0; nt < 2; ++nt)
#pragma unroll
        for (int m = 0; m < 4; ++m)
#pragma unroll
            for (int i = 0; i < 2; ++i) {
                const int row = R0 + mh * 64 + m * 16 + qrow + i * 8;
                *(float2*)(&g_drive[(size_t)row * SS + colg + nt * 8]) =
                    make_float2(acc[nt][m][2 * i], acc[nt][m][2 * i + 1]);
            }
}

// ---- powers: (A^T)^32 ----
__global__ void __launch_bounds__(256) k_powers() {
    __shared__ float sRow[2][SS];
    const int tid = threadIdx.x, k0 = blockIdx.x * 2;
    const float* src = g_At;
    float* dst = g_PA;
#pragma unroll 1
    for (int step = 0; step < 5; ++step) {
        sRow[0][tid] = src[(size_t)k0 * SS + tid];
        sRow[1][tid] = src[(size_t)(k0 + 1) * SS + tid];
        __syncthreads();
        float a0 = 0.f, a1 = 0.f;
#pragma unroll 4
        for (int j = 0; j < SS; ++j) {
            float b = src[(size_t)j * SS + tid];
            a0 = fmaf(sRow[0][j], b, a0);
            a1 = fmaf(sRow[1][j], b, a1);
        }
        dst[(size_t)k0 * SS + tid] = a0;
        dst[(size_t)(k0 + 1) * SS + tid] = a1;
        __syncthreads();
        if (tid == 0) {
            __threadfence();
            atomicAdd(&g_sync, 1u);
            unsigned tgt = 128u * (unsigned)(step + 1);
            while (*((volatile unsigned*)&g_sync) < tgt) { __nanosleep(64); }
        }
        __syncthreads();
        src = dst;
        dst = (dst == g_PA) ? g_PB : g_PA;
    }
}

// ---- warp-MMA scan (R16, proven): 512 threads; 2-CTA cluster per chunk ----
template <int MODE>
__global__ void __launch_bounds__(512) __cluster_dims__(2, 1, 1)
k_scan_mma(const float* __restrict__ Aw, float* __restrict__ out, int dup) {
    extern __shared__ __align__(16) char sm[];
    __shared__ float smax[17];
    const uint32_t sb = smem_u32(sm);
    const int tid = threadIdx.x;
    const int w = tid >> 5, lane = tid & 31;
    const uint32_t rank = ctarank();
    const int chunk = blockIdx.x >> 1;

    for (int e = tid; e < 128 * 256; e += 512) {
        int r = e >> 8, k = e & 255;
        float v = Aw[(size_t)((int)rank * 128 + r) * SS + k];
        __half q0 = __float2half_rn(v);
        __half q1 = __float2half_rn(v - __half2float(q0));
        *(__half*)(sm + SM_A0 + r * ROWB + k * 2) = q0;
        *(__half*)(sm + SM_A1 + r * ROWB + k * 2) = q1;
    }

    const float* xsrc = (MODE == 1) ? (g_drive + (size_t)(chunk * LCH) * BB * SS)
                                    : (g_xstart + (size_t)chunk * BB * SS);
    {
        float mymax = 0.f;
        for (int e = tid; e < 64 * 256; e += 512) mymax = fmaxf(mymax, fabsf(xsrc[e]));
#pragma unroll
        for (int o = 16; o; o >>= 1) mymax = fmaxf(mymax, __shfl_xor_sync(0xFFFFFFFFu, mymax, o));
        if (lane == 0) smax[w] = mymax;
        __syncthreads();
        if (tid == 0) {
            float m = smax[0];
#pragma unroll
            for (int i = 1; i < 16; ++i) m = fmaxf(m, smax[i]);
            smax[16] = m;
        }
        __syncthreads();
    }
    const float maxv = smax[16];
    const int ex = (maxv > 1e-30f) ? ilogbf(maxv) : 0;
    const float sc  = ldexpf(1.0f, -ex);
    const float inv = ldexpf(1.0f,  ex);

    for (int e = tid; e < 64 * 256; e += 512) {
        int b = e >> 8, k = e & 255;
        float v = xsrc[(size_t)b * SS + k] * sc;
        __half q0 = __float2half_rn(v);
        __half q1 = __float2half_rn(v - __half2float(q0));
        *(__half*)(sm + SM_X0 + b * ROWB + k * 2) = q0;
        *(__half*)(sm + SM_X1 + b * ROWB + k * 2) = q1;
    }
    __syncthreads();
    CLUSTER_SYNC();

    const uint32_t peerX = mapa_peer(sb, rank ^ 1u);
    const int qrow = lane >> 2;
    const uint32_t cb = (uint32_t)(lane & 3) * 4;
    const int n0 = (w & 7) * 16;
    const int mh = w >> 3;
    const int colg = (int)rank * 128 + n0 + 2 * (lane & 3);
    const int j0 = (MODE == 1) ? 1 : 0;

#pragma unroll 1
    for (int j = j0; j < LCH; ++j) {
        const int t = chunk * LCH + j;

        float acc[2][2][4];
#pragma unroll
        for (int nt = 0; nt < 2; ++nt)
#pragma unroll
            for (int m = 0; m < 2; ++m)
#pragma unroll
                for (int q = 0; q < 4; ++q) acc[nt][m][q] = 0.f;

        float2 dv[2][2][2];
        const float* drp = g_drive + (size_t)t * BB * SS;
#pragma unroll
        for (int nt = 0; nt < 2; ++nt)
#pragma unroll
            for (int m = 0; m < 2; ++m)
#pragma unroll
                for (int i = 0; i < 2; ++i)
                    dv[nt][m][i] = *(const float2*)(drp + (size_t)(mh * 32 + m * 16 + qrow + i * 8) * SS + colg + nt * 8);

#pragma unroll 2
        for (int kt = 0; kt < 16; ++kt) {
            const uint32_t kb = (uint32_t)kt * 32;
            uint32_t ax0[2][4], ax1[2][4];
#pragma unroll
            for (int m = 0; m < 2; ++m) {
                uint32_t b0a = sb + SM_X0 + (uint32_t)(mh * 32 + m * 16 + qrow) * ROWB + cb + kb;
                uint32_t b1a = sb + SM_X1 + (uint32_t)(mh * 32 + m * 16 + qrow) * ROWB + cb + kb;
                ax0[m][0] = lds_u32(b0a);
                ax0[m][1] = lds_u32(b0a + 8u * ROWB);
                ax0[m][2] = lds_u32(b0a + 16u);
                ax0[m][3] = lds_u32(b0a + 8u * ROWB + 16u);
                ax1[m][0] = lds_u32(b1a);
                ax1[m][1] = lds_u32(b1a + 8u * ROWB);
                ax1[m][2] = lds_u32(b1a + 16u);
                ax1[m][3] = lds_u32(b1a + 8u * ROWB + 16u);
            }
            uint32_t bb0[2][2], bb1[2][2];
#pragma unroll
            for (int nt = 0; nt < 2; ++nt) {
                uint32_t ba0 = sb + SM_A0 + (uint32_t)(n0 + nt * 8 + qrow) * ROWB + cb + kb;
                uint32_t ba1 = sb + SM_A1 + (uint32_t)(n0 + nt * 8 + qrow) * ROWB + cb + kb;
                bb0[nt][0] = lds_u32(ba0);
                bb0[nt][1] = lds_u32(ba0 + 16u);
                bb1[nt][0] = lds_u32(ba1);
                bb1[nt][1] = lds_u32(ba1 + 16u);
            }
#pragma unroll
            for (int nt = 0; nt < 2; ++nt)
#pragma unroll
                for (int m = 0; m < 2; ++m) {
                    mma16816(acc[nt][m], ax0[m], bb0[nt]);
                    mma16816(acc[nt][m], ax1[m], bb0[nt]);
                    mma16816(acc[nt][m], ax0[m], bb1[nt]);
                }
        }

        CLUSTER_SYNC();

#pragma unroll
        for (int nt = 0; nt < 2; ++nt)
#pragma unroll
            for (int m = 0; m < 2; ++m)
#pragma unroll
                for (int i = 0; i < 2; ++i) {
                    float v0 = acc[nt][m][2 * i]     + dv[nt][m][i].x * sc;
                    float v1 = acc[nt][m][2 * i + 1] + dv[nt][m][i].y * sc;
                    const int row  = mh * 32 + m * 16 + qrow + i * 8;
                    const int kcol = colg + nt * 8;

                    if (MODE == 3) {
                        float* o1 = out + (size_t)t * BB * SS + (size_t)row * SS + kcol;
                        *(float2*)o1 = make_float2(v0 * inv, v1 * inv);
                        if (dup) *(float2*)(o1 + (size_t)TBS) = make_float2(v0 * inv, v1 * inv);
                    }
                    if (MODE == 1 && j == LCH - 1) {
                        float* le = g_localEnd + (size_t)chunk * BB * SS + (size_t)row * SS + kcol;
                        *(float2*)le = make_float2(v0 * inv, v1 * inv);
                    }

                    __half h0 = __float2half_rn(v0);
                    __half h1 = __float2half_rn(v1);
                    uint32_t p0 = h2pack(v0, v1);
                    uint32_t p1 = h2pack(v0 - __half2float(h0), v1 - __half2float(h1));
                    const uint32_t off = (uint32_t)row * ROWB + (uint32_t)kcol * 2;
                    *(uint32_t*)(sm + SM_X0 + off) = p0;
                    *(uint32_t*)(sm + SM_X1 + off) = p1;
                    st_cluster_b32(peerX + SM_X0 + off, p0);
                    st_cluster_b32(peerX + SM_X1 + off, p1);
                }

        CLUSTER_SYNC();
    }
}

// ---- pass2: boundary recurrence (fp32, proven) ----
__global__ void __launch_bounds__(128) k_pass2(const float* __restrict__ x0) {
    const int b0 = blockIdx.x * 2;
    const int s0 = 2 * threadIdx.x;
    __shared__ __align__(8) float sxp[SS][2];

    float2 vA = *(const float2*)(&x0[(size_t)b0 * SS + s0]);
    float2 vB = *(const float2*)(&x0[(size_t)(b0 + 1) * SS + s0]);
    sxp[s0][0] = vA.x;     sxp[s0][1] = vB.x;
    sxp[s0 + 1][0] = vA.y; sxp[s0 + 1][1] = vB.y;
    *(float2*)(&g_xstart[((size_t)b0) * SS + s0])       = vA;
    *(float2*)(&g_xstart[((size_t)(b0 + 1)) * SS + s0]) = vB;
    __syncthreads();

#pragma unroll 1
    for (int c = 1; c < CCH; ++c) {
        float2 eA = *(const float2*)(&g_localEnd[((size_t)(c - 1) * BB + b0) * SS + s0]);
        float2 eB = *(const float2*)(&g_localEnd[((size_t)(c - 1) * BB + b0 + 1) * SS + s0]);
        unsigned long long a0[4], a1[4];
#pragma unroll
        for (int u = 0; u < 4; ++u) { a0[u] = 0ull; a1[u] = 0ull; }
        const float* wp = g_PA + s0;
#pragma unroll 2
        for (int k = 0; k < SS; k += 4) {
#pragma unroll
            for (int u = 0; u < 4; ++u) {
                float2 wv = *(const float2*)(wp + (size_t)(k + u) * SS);
                unsigned long long xp = *(const unsigned long long*)(&sxp[k + u][0]);
                fma2(a0[u], xp, pack2(wv.x, wv.x));
                fma2(a1[u], xp, pack2(wv.y, wv.y));
            }
        }
        add2(a0[0], a0[1]); add2(a0[2], a0[3]); add2(a0[0], a0[2]);
        add2(a1[0], a1[1]); add2(a1[2], a1[3]); add2(a1[0], a1[2]);
        float2 f0 = unpack2(a0[0]), f1 = unpack2(a1[0]);
        f0.x += eA.x; f0.y += eB.x;
        f1.x += eA.y; f1.y += eB.y;
        __syncthreads();
        sxp[s0][0] = f0.x;     sxp[s0][1] = f0.y;
        sxp[s0 + 1][0] = f1.x; sxp[s0 + 1][1] = f1.y;
        __syncthreads();
        *(float2*)(&g_xstart[((size_t)c * BB + b0) * SS + s0])     = make_float2(f0.x, f1.x);
        *(float2*)(&g_xstart[((size_t)c * BB + b0 + 1) * SS + s0]) = make_float2(f0.y, f1.y);
    }
}

// ---- launcher ----
extern "C" void kernel_launch(void* const* d_in, const int* in_sizes, int n_in,
                              void* d_out, int out_size) {
    const float* x  = (const float*)d_in[0];
    const float* U  = (const float*)d_in[1];
    const float* D  = (const float*)d_in[2];
    const float* Aw = (const float*)d_in[3];
    const float* Bw = (const float*)d_in[4];
    const float* Ew = (const float*)d_in[5];
    float* out = (float*)d_out;
    int dup = (out_size >= 2 * TBS) ? 1 : 0;

    cudaFuncSetAttribute(k_drive_mma, cudaFuncAttributeMaxDynamicSharedMemorySize, DM_TOT);
    cudaFuncSetAttribute(k_scan_mma<1>, cudaFuncAttributeMaxDynamicSharedMemorySize, SM_SCAN_TOT);
    cudaFuncSetAttribute(k_scan_mma<3>, cudaFuncAttributeMaxDynamicSharedMemorySize, SM_SCAN_TOT);

    k_prep<<<(SS * SS + 255) / 256, 256>>>(Aw);                        // 0
    k_drive_mma<<<(TT * BB / 128) * 2, 512, DM_TOT>>>(U, D, Bw, Ew);   // 1
    k_powers<<<SS / 2, 256>>>();                                       // 2
    k_scan_mma<1><<<(CCH - 1) * 2, 512, SM_SCAN_TOT>>>(Aw, out, 0);    // 3 (pass1)
    k_pass2<<<BB / 2, 128>>>(x);                                       // 4
    k_scan_mma<3><<<CCH * 2, 512, SM_SCAN_TOT>>>(Aw, out, dup);        // 5 (pass3)
}